// round 16
// baseline (speedup 1.0000x reference)
#include <cuda_runtime.h>
#include <cuda_bf16.h>
#include <cuda_fp16.h>
#include <math.h>
#include <stdint.h>

#define BB 4096
#define IND 2048
#define SS 8
#define DD 256
#define KK 8192
#define SD 2048   // S*D

#define CAP 96
#define CAPR 24
#define MARGIN 2e-4f

typedef unsigned long long u64;

// ------------- device-global scratch -------------------------------------
__device__ float g_z[(size_t)BB * SD];
__device__ float g_quant[(size_t)BB * SD];
__device__ float g_recon[(size_t)BB * IND];
__device__ float g_zsq[BB * SS];
__device__ float g_esq[SS * KK];
__device__ int   g_codes[BB * SS];
__device__ float g_counts[SS * KK];
__device__ int   g_flags[BB * SS];
__device__ __nv_bfloat16 g_zb[(size_t)BB * SD];
__device__ __nv_bfloat16 g_cbb[(size_t)SS * KK * DD];
// fp16 split operands (decoder only — encoder must stay bit-exact fp32)
__device__ __half g_dwh[(size_t)IND * SD];
__device__ __half g_dwl[(size_t)IND * SD];
__device__ __half g_qh[(size_t)BB * SD];
__device__ __half g_ql[(size_t)BB * SD];

// ------------- f32x2 packed-FMA helpers ----------------------------------
__device__ __forceinline__ u64 pk2(float x, float y) {
  u64 r;
  asm("mov.b64 %0, {%1, %2};" : "=l"(r) : "f"(x), "f"(y));
  return r;
}
__device__ __forceinline__ void fma2(u64& d, u64 a, u64 b) {
  asm("fma.rn.f32x2 %0, %1, %2, %0;" : "+l"(d) : "l"(a), "l"(b));
}
__device__ __forceinline__ void upk2(float& x, float& y, u64 a) {
  asm("mov.b64 {%0, %1}, %2;" : "=f"(x), "=f"(y) : "l"(a));
}

// ------------- ordered-float <-> uint (monotone) -------------------------
__device__ __forceinline__ unsigned ordf(float f) {
  unsigned u = __float_as_uint(f);
  return (u & 0x80000000u) ? ~u : (u | 0x80000000u);
}
__device__ __forceinline__ float unordf(unsigned u) {
  unsigned b = (u & 0x80000000u) ? (u & 0x7FFFFFFFu) : ~u;
  return __uint_as_float(b);
}
__device__ __forceinline__ u64 packdk(float d, int k) {
  unsigned u = __float_as_uint(d);
  u = (u & 0x80000000u) ? ~u : (u | 0x80000000u);
  return ((u64)u << 32) | (unsigned)k;
}

// ------------- fp32 GEMM (R14 champion, FROZEN chain) + zb epilogue ------
__global__ __launch_bounds__(256, 2) void gemm128x2(
    const float* __restrict__ A, const float* __restrict__ Wt,
    const float* __restrict__ bias, float* __restrict__ C,
    __nv_bfloat16* __restrict__ Cb, int M, int N, int Kd) {
  __shared__ __align__(16) float xs[2][16][132];
  __shared__ __align__(16) float ws[2][16][132];
  int tid = threadIdx.x;
  int ty = tid >> 4, tx = tid & 15;
  int row0 = blockIdx.y << 7, col0 = blockIdx.x << 7;
  int lrow = tid >> 1, lk8 = (tid & 1) << 3;

  u64 acc[8][4];
#pragma unroll
  for (int i = 0; i < 8; i++)
#pragma unroll
    for (int j = 0; j < 4; j++) acc[i][j] = 0ull;

  const float* Ap = A + (size_t)(row0 + lrow) * Kd + lk8;
  const float* Wp = Wt + (size_t)(col0 + lrow) * Kd + lk8;

  {
    float4 a0 = *(const float4*)(Ap);
    float4 a1 = *(const float4*)(Ap + 4);
    float4 b0 = *(const float4*)(Wp);
    float4 b1 = *(const float4*)(Wp + 4);
    xs[0][lk8 + 0][lrow] = a0.x; xs[0][lk8 + 1][lrow] = a0.y;
    xs[0][lk8 + 2][lrow] = a0.z; xs[0][lk8 + 3][lrow] = a0.w;
    xs[0][lk8 + 4][lrow] = a1.x; xs[0][lk8 + 5][lrow] = a1.y;
    xs[0][lk8 + 6][lrow] = a1.z; xs[0][lk8 + 7][lrow] = a1.w;
    ws[0][lk8 + 0][lrow] = b0.x; ws[0][lk8 + 1][lrow] = b0.y;
    ws[0][lk8 + 2][lrow] = b0.z; ws[0][lk8 + 3][lrow] = b0.w;
    ws[0][lk8 + 4][lrow] = b1.x; ws[0][lk8 + 5][lrow] = b1.y;
    ws[0][lk8 + 6][lrow] = b1.z; ws[0][lk8 + 7][lrow] = b1.w;
  }
  __syncthreads();

  int NC = Kd >> 4;
  for (int ch = 0; ch < NC; ch++) {
    int cur = ch & 1, nxt = cur ^ 1;
    float4 a0, a1, b0, b1;
    bool more = (ch + 1 < NC);
    if (more) {
      int k0 = (ch + 1) << 4;
      a0 = *(const float4*)(Ap + k0);
      a1 = *(const float4*)(Ap + k0 + 4);
      b0 = *(const float4*)(Wp + k0);
      b1 = *(const float4*)(Wp + k0 + 4);
    }
#pragma unroll
    for (int kk = 0; kk < 16; kk++) {
      float4 av0 = *(const float4*)&xs[cur][kk][ty << 2];
      float4 av1 = *(const float4*)&xs[cur][kk][64 + (ty << 2)];
      float4 bv0 = *(const float4*)&ws[cur][kk][tx << 2];
      float4 bv1 = *(const float4*)&ws[cur][kk][64 + (tx << 2)];
      u64 b2[4];
      b2[0] = pk2(bv0.x, bv0.y); b2[1] = pk2(bv0.z, bv0.w);
      b2[2] = pk2(bv1.x, bv1.y); b2[3] = pk2(bv1.z, bv1.w);
      float ar[8] = {av0.x, av0.y, av0.z, av0.w, av1.x, av1.y, av1.z, av1.w};
#pragma unroll
      for (int i = 0; i < 8; i++) {
        u64 a2 = pk2(ar[i], ar[i]);
#pragma unroll
        for (int j = 0; j < 4; j++) fma2(acc[i][j], a2, b2[j]);
      }
    }
    if (more) {
      xs[nxt][lk8 + 0][lrow] = a0.x; xs[nxt][lk8 + 1][lrow] = a0.y;
      xs[nxt][lk8 + 2][lrow] = a0.z; xs[nxt][lk8 + 3][lrow] = a0.w;
      xs[nxt][lk8 + 4][lrow] = a1.x; xs[nxt][lk8 + 5][lrow] = a1.y;
      xs[nxt][lk8 + 6][lrow] = a1.z; xs[nxt][lk8 + 7][lrow] = a1.w;
      ws[nxt][lk8 + 0][lrow] = b0.x; ws[nxt][lk8 + 1][lrow] = b0.y;
      ws[nxt][lk8 + 2][lrow] = b0.z; ws[nxt][lk8 + 3][lrow] = b0.w;
      ws[nxt][lk8 + 4][lrow] = b1.x; ws[nxt][lk8 + 5][lrow] = b1.y;
      ws[nxt][lk8 + 6][lrow] = b1.z; ws[nxt][lk8 + 7][lrow] = b1.w;
      __syncthreads();
    }
  }
#pragma unroll
  for (int i = 0; i < 8; i++) {
    int r = row0 + ((i < 4) ? ((ty << 2) + i) : (64 + (ty << 2) + i - 4));
    int c0 = col0 + (tx << 2);
    int c1 = col0 + 64 + (tx << 2);
    float o[8];
#pragma unroll
    for (int j = 0; j < 4; j++) upk2(o[2 * j], o[2 * j + 1], acc[i][j]);
    o[0] += bias[c0]; o[1] += bias[c0 + 1];
    o[2] += bias[c0 + 2]; o[3] += bias[c0 + 3];
    o[4] += bias[c1]; o[5] += bias[c1 + 1];
    o[6] += bias[c1 + 2]; o[7] += bias[c1 + 3];
    *(float4*)(C + (size_t)r * N + c0) = make_float4(o[0], o[1], o[2], o[3]);
    *(float4*)(C + (size_t)r * N + c1) = make_float4(o[4], o[5], o[6], o[7]);
    __nv_bfloat162 p0 = __floats2bfloat162_rn(o[0], o[1]);
    __nv_bfloat162 p1 = __floats2bfloat162_rn(o[2], o[3]);
    __nv_bfloat162 p2 = __floats2bfloat162_rn(o[4], o[5]);
    __nv_bfloat162 p3 = __floats2bfloat162_rn(o[6], o[7]);
    *(uint2*)(Cb + (size_t)r * N + c0) = make_uint2(*(uint32_t*)&p0, *(uint32_t*)&p1);
    *(uint2*)(Cb + (size_t)r * N + c1) = make_uint2(*(uint32_t*)&p2, *(uint32_t*)&p3);
  }
}

// ------------- split fp32 -> fp16 hi/lo with exact pow2 pre-scale --------
__global__ void split_kernel(const float* __restrict__ in,
                             __half* __restrict__ hi, __half* __restrict__ lo,
                             float scale, int n4) {
  int i = blockIdx.x * blockDim.x + threadIdx.x;
  if (i < n4) {
    float4 v = ((const float4*)in)[i];
    v.x *= scale; v.y *= scale; v.z *= scale; v.w *= scale;
    __half hx = __float2half_rn(v.x), hy = __float2half_rn(v.y);
    __half hz = __float2half_rn(v.z), hw = __float2half_rn(v.w);
    __half lx = __float2half_rn(v.x - __half2float(hx));
    __half ly = __float2half_rn(v.y - __half2float(hy));
    __half lz = __float2half_rn(v.z - __half2float(hz));
    __half lw = __float2half_rn(v.w - __half2float(hw));
    __half2 h0 = __halves2half2(hx, hy), h1 = __halves2half2(hz, hw);
    __half2 l0 = __halves2half2(lx, ly), l1 = __halves2half2(lz, lw);
    ((uint2*)hi)[i] = make_uint2(*(uint32_t*)&h0, *(uint32_t*)&h1);
    ((uint2*)lo)[i] = make_uint2(*(uint32_t*)&l0, *(uint32_t*)&l1);
  }
}

// ------------- fp16 mma helper -------------------------------------------
__device__ __forceinline__ void mmaf16(float* c, const uint32_t* a,
                                       const uint32_t* b) {
  asm volatile(
      "mma.sync.aligned.m16n8k16.row.col.f32.f16.f16.f32 "
      "{%0,%1,%2,%3}, {%4,%5,%6,%7}, {%8,%9}, {%0,%1,%2,%3};"
      : "+f"(c[0]), "+f"(c[1]), "+f"(c[2]), "+f"(c[3])
      : "r"(a[0]), "r"(a[1]), "r"(a[2]), "r"(a[3]), "r"(b[0]), "r"(b[1]));
}

// ------------- 3-product fp16-split GEMM (decoder) -----------------------
__global__ __launch_bounds__(256) void gemm3h(
    const __half* __restrict__ Ah, const __half* __restrict__ Al,
    const __half* __restrict__ Wh, const __half* __restrict__ Wl,
    const float* __restrict__ bias, float* __restrict__ C, float inv, int M,
    int N, int Kd) {
  __shared__ __align__(16) __half Ahs[128][40];
  __shared__ __align__(16) __half Als[128][40];
  __shared__ __align__(16) __half Whs[128][40];
  __shared__ __align__(16) __half Wls[128][40];
  int tid = threadIdx.x;
  int wid = tid >> 5, lane = tid & 31;
  int gid = lane >> 2, tig = lane & 3;
  int wm = wid & 1, wn = wid >> 1;
  int row0 = blockIdx.y << 7, col0 = blockIdx.x << 7;

  float acc[4][4][4];
#pragma unroll
  for (int mf = 0; mf < 4; mf++)
#pragma unroll
    for (int nf = 0; nf < 4; nf++)
#pragma unroll
      for (int q = 0; q < 4; q++) acc[mf][nf][q] = 0.f;

  for (int k0 = 0; k0 < Kd; k0 += 32) {
    __syncthreads();
#pragma unroll
    for (int l = 0; l < 2; l++) {
      int idx = tid + l * 256;
      int r = idx >> 2, c8 = (idx & 3) * 8;
      size_t ga = (size_t)(row0 + r) * Kd + k0 + c8;
      size_t gw = (size_t)(col0 + r) * Kd + k0 + c8;
      *(uint4*)&Ahs[r][c8] = *(const uint4*)(Ah + ga);
      *(uint4*)&Als[r][c8] = *(const uint4*)(Al + ga);
      *(uint4*)&Whs[r][c8] = *(const uint4*)(Wh + gw);
      *(uint4*)&Wls[r][c8] = *(const uint4*)(Wl + gw);
    }
    __syncthreads();

#pragma unroll
    for (int kk = 0; kk < 2; kk++) {
      int k16 = kk * 16;
      uint32_t ah[4][4], al[4][4];
#pragma unroll
      for (int mf = 0; mf < 4; mf++) {
        int R = wm * 64 + mf * 16;
        ah[mf][0] = *(const uint32_t*)&Ahs[R + gid][k16 + 2 * tig];
        ah[mf][1] = *(const uint32_t*)&Ahs[R + gid + 8][k16 + 2 * tig];
        ah[mf][2] = *(const uint32_t*)&Ahs[R + gid][k16 + 8 + 2 * tig];
        ah[mf][3] = *(const uint32_t*)&Ahs[R + gid + 8][k16 + 8 + 2 * tig];
        al[mf][0] = *(const uint32_t*)&Als[R + gid][k16 + 2 * tig];
        al[mf][1] = *(const uint32_t*)&Als[R + gid + 8][k16 + 2 * tig];
        al[mf][2] = *(const uint32_t*)&Als[R + gid][k16 + 8 + 2 * tig];
        al[mf][3] = *(const uint32_t*)&Als[R + gid + 8][k16 + 8 + 2 * tig];
      }
#pragma unroll
      for (int nf = 0; nf < 4; nf++) {
        int Cc = wn * 32 + nf * 8;
        uint32_t bh[2], bl[2];
        bh[0] = *(const uint32_t*)&Whs[Cc + gid][k16 + 2 * tig];
        bh[1] = *(const uint32_t*)&Whs[Cc + gid][k16 + 8 + 2 * tig];
        bl[0] = *(const uint32_t*)&Wls[Cc + gid][k16 + 2 * tig];
        bl[1] = *(const uint32_t*)&Wls[Cc + gid][k16 + 8 + 2 * tig];
#pragma unroll
        for (int mf = 0; mf < 4; mf++) {
          mmaf16(acc[mf][nf], ah[mf], bh);
          mmaf16(acc[mf][nf], ah[mf], bl);
          mmaf16(acc[mf][nf], al[mf], bh);
        }
      }
    }
  }

#pragma unroll
  for (int mf = 0; mf < 4; mf++) {
    int r0 = row0 + wm * 64 + mf * 16 + gid;
#pragma unroll
    for (int nf = 0; nf < 4; nf++) {
      int c = col0 + wn * 32 + nf * 8 + 2 * tig;
      float b0 = bias[c], b1 = bias[c + 1];
      float2 lo = make_float2(acc[mf][nf][0] * inv + b0,
                              acc[mf][nf][1] * inv + b1);
      float2 hi = make_float2(acc[mf][nf][2] * inv + b0,
                              acc[mf][nf][3] * inv + b1);
      *(float2*)(C + (size_t)r0 * N + c) = lo;
      *(float2*)(C + (size_t)(r0 + 8) * N + c) = hi;
    }
  }
}

// ------------- row sum-of-squares (order is load-bearing) ----------------
__global__ void rowsq_kernel(const float* __restrict__ in,
                             float* __restrict__ out, int nrows) {
  int w = (blockIdx.x * blockDim.x + threadIdx.x) >> 5;
  int lane = threadIdx.x & 31;
  if (w >= nrows) return;
  const float* p = in + (size_t)w * DD;
  float s = 0.f;
#pragma unroll
  for (int i = 0; i < 8; i++) { float v = p[lane + 32 * i]; s += v * v; }
#pragma unroll
  for (int o = 16; o; o >>= 1) s += __shfl_xor_sync(0xffffffffu, s, o);
  if (lane == 0) out[w] = s;
}

__global__ void zero_kernel(float* __restrict__ p, int n) {
  int i = blockIdx.x * blockDim.x + threadIdx.x;
  if (i < n) p[i] = 0.f;
}

__global__ void tobf16_kernel(const float* __restrict__ in,
                              __nv_bfloat16* __restrict__ out, int n4) {
  int i = blockIdx.x * blockDim.x + threadIdx.x;
  if (i < n4) {
    float4 v = ((const float4*)in)[i];
    __nv_bfloat162 a = __floats2bfloat162_rn(v.x, v.y);
    __nv_bfloat162 b = __floats2bfloat162_rn(v.z, v.w);
    ((uint2*)out)[i] = make_uint2(*(uint32_t*)&a, *(uint32_t*)&b);
  }
}

// ------------- bf16 HMMA mma.sync helper ---------------------------------
__device__ __forceinline__ void mma16816(float* c, const uint32_t* a,
                                         const uint32_t* b) {
  asm volatile(
      "mma.sync.aligned.m16n8k16.row.col.f32.bf16.bf16.f32 "
      "{%0,%1,%2,%3}, {%4,%5,%6,%7}, {%8,%9}, {%0,%1,%2,%3};"
      : "+f"(c[0]), "+f"(c[1]), "+f"(c[2]), "+f"(c[3])
      : "r"(a[0]), "r"(a[1]), "r"(a[2]), "r"(a[3]), "r"(b[0]), "r"(b[1]));
}

// ------------- FUSED: cross GEMM + running-max filter + exact argmin -----
// grid (BB/128, SS); block 256 (8 warps). Per block: 128 rows x all 8192
// codes. A tile resident in smem; B staged per 128-code tile in 64-k chunks.
// dyn smem layout (bytes):
//   [0, 67584)       As 128 x 264 bf16
//   [67584, 86016)   Bs 128 x 72 bf16
//   [86016, 86528)   rowmax 128 u32 (ordered-float)
//   [86528, 87040)   cnt 128 int
//   [87040, 99328)   cand 128 x CAPR int
#define FSM_TOT 99328
__global__ __launch_bounds__(256) void cross_argmin_kernel(
    const __nv_bfloat16* __restrict__ zb, const __nv_bfloat16* __restrict__ cbb,
    const float* __restrict__ z, const float* __restrict__ cb,
    const float* __restrict__ zsq, const float* __restrict__ esq,
    int* __restrict__ codes, int* __restrict__ flags) {
  extern __shared__ __align__(16) char smraw[];
  __nv_bfloat16 (*As)[264] = (__nv_bfloat16(*)[264])smraw;
  __nv_bfloat16 (*Bs)[72] = (__nv_bfloat16(*)[72])(smraw + 67584);
  unsigned* rowmax = (unsigned*)(smraw + 86016);
  int* cnt = (int*)(smraw + 86528);
  int (*cand)[CAPR] = (int(*)[CAPR])(smraw + 87040);

  int tid = threadIdx.x;
  int wid = tid >> 5, lane = tid & 31;
  int gid = lane >> 2, tig = lane & 3;
  int wm = wid & 1, wn = wid >> 1;
  int s = blockIdx.y, b0 = blockIdx.x << 7;

  // load whole A tile: 128 rows x 256 bf16
#pragma unroll
  for (int l = 0; l < 16; l++) {
    int idx = tid + l * 256;
    int r = idx >> 5, c8 = idx & 31;
    *(uint4*)&As[r][c8 * 8] =
        *(const uint4*)(zb + (size_t)(b0 + r) * SD + s * DD + c8 * 8);
  }
  if (tid < 128) { rowmax[tid] = 0u; cnt[tid] = 0; }
  __syncthreads();

  for (int kt = 0; kt < KK / 128; kt++) {
    int k0 = kt << 7;
    float acc[4][4][4];
#pragma unroll
    for (int mf = 0; mf < 4; mf++)
#pragma unroll
      for (int nf = 0; nf < 4; nf++)
#pragma unroll
        for (int q = 0; q < 4; q++) acc[mf][nf][q] = 0.f;

    for (int kc = 0; kc < 4; kc++) {
      __syncthreads();
#pragma unroll
      for (int l = 0; l < 4; l++) {
        int idx = tid + l * 256;
        int r = idx >> 3, c8 = idx & 7;
        *(uint4*)&Bs[r][c8 * 8] = *(const uint4*)(
            cbb + ((size_t)s * KK + k0 + r) * DD + kc * 64 + c8 * 8);
      }
      __syncthreads();
      int koff = kc * 64;
#pragma unroll
      for (int kk = 0; kk < 4; kk++) {
        int k16 = koff + kk * 16;
        uint32_t a[4][4];
#pragma unroll
        for (int mf = 0; mf < 4; mf++) {
          int R = wm * 64 + mf * 16;
          a[mf][0] = *(const uint32_t*)&As[R + gid][k16 + 2 * tig];
          a[mf][1] = *(const uint32_t*)&As[R + gid + 8][k16 + 2 * tig];
          a[mf][2] = *(const uint32_t*)&As[R + gid][k16 + 8 + 2 * tig];
          a[mf][3] = *(const uint32_t*)&As[R + gid + 8][k16 + 8 + 2 * tig];
        }
        int k16b = kk * 16;
#pragma unroll
        for (int nf = 0; nf < 4; nf++) {
          int C = wn * 32 + nf * 8;
          uint32_t b[2];
          b[0] = *(const uint32_t*)&Bs[C + gid][k16b + 2 * tig];
          b[1] = *(const uint32_t*)&Bs[C + gid][k16b + 8 + 2 * tig];
#pragma unroll
          for (int mf = 0; mf < 4; mf++) mma16816(acc[mf][nf], a[mf], b);
        }
      }
    }
    // running-max update
#pragma unroll
    for (int mf = 0; mf < 4; mf++) {
      int r1 = wm * 64 + mf * 16 + gid;
      float m1 = acc[mf][0][0], m2 = acc[mf][0][2];
#pragma unroll
      for (int nf = 0; nf < 4; nf++) {
        m1 = fmaxf(m1, fmaxf(acc[mf][nf][0], acc[mf][nf][1]));
        m2 = fmaxf(m2, fmaxf(acc[mf][nf][2], acc[mf][nf][3]));
      }
      atomicMax(&rowmax[r1], ordf(m1));
      atomicMax(&rowmax[r1 + 8], ordf(m2));
    }
    __syncthreads();
    // candidate collection (threshold from running max — monotone-safe)
#pragma unroll
    for (int mf = 0; mf < 4; mf++) {
      int r1 = wm * 64 + mf * 16 + gid;
      float th1 = unordf(rowmax[r1]) - MARGIN;
      float th2 = unordf(rowmax[r1 + 8]) - MARGIN;
#pragma unroll
      for (int nf = 0; nf < 4; nf++) {
        int col = k0 + wn * 32 + nf * 8 + 2 * tig;
        if (acc[mf][nf][0] >= th1) {
          int p = atomicAdd(&cnt[r1], 1);
          if (p < CAPR) cand[r1][p] = col;
        }
        if (acc[mf][nf][1] >= th1) {
          int p = atomicAdd(&cnt[r1], 1);
          if (p < CAPR) cand[r1][p] = col + 1;
        }
        if (acc[mf][nf][2] >= th2) {
          int p = atomicAdd(&cnt[r1 + 8], 1);
          if (p < CAPR) cand[r1 + 8][p] = col;
        }
        if (acc[mf][nf][3] >= th2) {
          int p = atomicAdd(&cnt[r1 + 8], 1);
          if (p < CAPR) cand[r1 + 8][p] = col + 1;
        }
      }
    }
  }
  __syncthreads();
  if (tid < 128) flags[s * BB + b0 + tid] = (cnt[tid] > CAPR) ? 1 : 0;
  __syncthreads();

  // exact recheck: warp wid owns rows wid*16 .. +15
  for (int rr = 0; rr < 16; rr++) {
    int r = wid * 16 + rr;
    int n = cnt[r];
    if (n > CAPR) continue;   // fallback kernel will handle
    int b = b0 + r;
    u64 best = ~0ull;
    if (lane < n) {
      int k = cand[r][lane];
      const float* e = cb + ((size_t)s * KK + k) * DD;
      const float* zr = z + (size_t)b * SD + s * DD;
      float a = 0.f;
#pragma unroll 8
      for (int d = 0; d < DD; d += 4) {
        float4 ev = *(const float4*)(e + d);
        a = fmaf(zr[d + 0], ev.x, a);
        a = fmaf(zr[d + 1], ev.y, a);
        a = fmaf(zr[d + 2], ev.z, a);
        a = fmaf(zr[d + 3], ev.w, a);
      }
      float t = zsq[b * SS + s] + esq[s * KK + k];
      best = packdk(t - 2.0f * a, k);
    }
#pragma unroll
    for (int o = 16; o; o >>= 1) {
      u64 v = __shfl_xor_sync(0xffffffffu, best, o);
      if (v < best) best = v;
    }
    if (lane == 0) codes[b * SS + s] = (int)(best & 0xffffffffULL);
  }
}

// ------------- fallback: full exact scan for overflowed rows -------------
__global__ __launch_bounds__(256) void fallback_kernel(
    const float* __restrict__ z, const float* __restrict__ cb,
    const float* __restrict__ zsq, const float* __restrict__ esq,
    int* __restrict__ codes, const int* __restrict__ flags) {
  if (!flags[blockIdx.x]) return;
  __shared__ float zrow[DD];
  __shared__ u64 red[256];
  int srow = blockIdx.x;
  int s = srow >> 12, b = srow & 4095;
  int tid = threadIdx.x;
  zrow[tid] = z[(size_t)b * SD + s * DD + tid];
  __syncthreads();
  float zsqv = zsq[b * SS + s];
  u64 best = ~0ull;
  for (int j = 0; j < 32; j++) {
    int k = tid + j * 256;
    const float* e = cb + ((size_t)s * KK + k) * DD;
    float acc = 0.f;
#pragma unroll 8
    for (int d = 0; d < DD; d += 4) {
      float4 ev = *(const float4*)(e + d);
      acc = fmaf(zrow[d + 0], ev.x, acc);
      acc = fmaf(zrow[d + 1], ev.y, acc);
      acc = fmaf(zrow[d + 2], ev.z, acc);
      acc = fmaf(zrow[d + 3], ev.w, acc);
    }
    float dv = (zsqv + esq[s * KK + k]) - 2.0f * acc;
    u64 p = packdk(dv, k);
    if (p < best) best = p;
  }
  red[tid] = best;
  __syncthreads();
  for (int o = 128; o; o >>= 1) {
    if (tid < o) { u64 v = red[tid + o]; if (v < red[tid]) red[tid] = v; }
    __syncthreads();
  }
  if (tid == 0) codes[b * SS + s] = (int)(red[0] & 0xffffffffULL);
}

// ------------- tail kernels ----------------------------------------------
__global__ void gather_kernel(const float* __restrict__ cb,
                              const int* __restrict__ codes,
                              float* __restrict__ quant) {
  int i = blockIdx.x * blockDim.x + threadIdx.x;
  int b = i >> 9, rem = i & 511;
  int s = rem >> 6, d4 = rem & 63;
  int code = codes[b * SS + s];
  float4 v = *(const float4*)(cb + ((size_t)(s * KK + code)) * DD + (d4 << 2));
  *(float4*)(quant + (size_t)b * SD + s * DD + (d4 << 2)) = v;
}

__global__ void count_kernel(const int* __restrict__ codes,
                             float* __restrict__ counts) {
  int i = blockIdx.x * blockDim.x + threadIdx.x;
  if (i < BB * SS) {
    int s = i & 7;
    atomicAdd(&counts[s * KK + codes[i]], 1.0f);
  }
}

__global__ void perp_kernel(const float* __restrict__ counts,
                            float* __restrict__ outp) {
  __shared__ float sh[256];
  __shared__ float perps;
  int tid = threadIdx.x;
  if (tid == 0) perps = 0.f;
  for (int s = 0; s < SS; s++) {
    float local = 0.f;
    for (int k = tid; k < KK; k += 256) {
      float p = counts[s * KK + k] * (1.0f / BB);
      local += p * logf(p + 1e-10f);
    }
    sh[tid] = local;
    __syncthreads();
    for (int o = 128; o; o >>= 1) {
      if (tid < o) sh[tid] += sh[tid + o];
      __syncthreads();
    }
    if (tid == 0) perps += expf(-sh[0]);
    __syncthreads();
  }
  if (tid == 0) *outp = perps * (1.0f / SS);
}

__global__ void copy4_kernel(float* __restrict__ dst,
                             const float* __restrict__ src, int n4) {
  int i = blockIdx.x * blockDim.x + threadIdx.x;
  if (i < n4) ((float4*)dst)[i] = ((const float4*)src)[i];
}

__global__ void codesf_kernel(float* __restrict__ dst,
                              const int* __restrict__ codes, int n) {
  int i = blockIdx.x * blockDim.x + threadIdx.x;
  if (i < n) dst[i] = (float)codes[i];
}

// --------------------------------------------------------------------------
extern "C" void kernel_launch(void* const* d_in, const int* in_sizes, int n_in,
                              void* d_out, int out_size) {
  const float* x     = (const float*)d_in[0];
  const float* enc_w = (const float*)d_in[1];
  const float* enc_b = (const float*)d_in[2];
  const float* cb    = (const float*)d_in[3];
  const float* dec_w = (const float*)d_in[4];
  const float* dec_b = (const float*)d_in[5];

  float *z, *quant, *recon, *zsq, *esq, *counts;
  int *codes, *flags;
  __nv_bfloat16 *zb, *cbb;
  __half *dwh, *dwl, *qh, *ql;
  cudaGetSymbolAddress((void**)&z, g_z);
  cudaGetSymbolAddress((void**)&quant, g_quant);
  cudaGetSymbolAddress((void**)&recon, g_recon);
  cudaGetSymbolAddress((void**)&zsq, g_zsq);
  cudaGetSymbolAddress((void**)&esq, g_esq);
  cudaGetSymbolAddress((void**)&counts, g_counts);
  cudaGetSymbolAddress((void**)&codes, g_codes);
  cudaGetSymbolAddress((void**)&flags, g_flags);
  cudaGetSymbolAddress((void**)&zb, g_zb);
  cudaGetSymbolAddress((void**)&cbb, g_cbb);
  cudaGetSymbolAddress((void**)&dwh, g_dwh);
  cudaGetSymbolAddress((void**)&dwl, g_dwl);
  cudaGetSymbolAddress((void**)&qh, g_qh);
  cudaGetSymbolAddress((void**)&ql, g_ql);

  const int offQ = BB * IND;
  const int offC = offQ + BB * SD;
  const int offP = offC + BB * SS;
  float* out = (float*)d_out;
  float* reconDst = (out_size >= offQ) ? out : recon;

  cudaFuncSetAttribute(cross_argmin_kernel,
                       cudaFuncAttributeMaxDynamicSharedMemorySize, FSM_TOT);

  // 1. encoder (FROZEN fp32 chain) — also emits zb
  gemm128x2<<<dim3(SD / 128, BB / 128), 256>>>(x, enc_w, enc_b, z, zb,
                                               BB, SD, IND);
  // 2. norms (unchanged reduction order)
  rowsq_kernel<<<BB * SS / 8, 256>>>(z, zsq, BB * SS);
  rowsq_kernel<<<SS * KK / 8, 256>>>(cb, esq, SS * KK);
  // 3. bf16 codebooks for filter
  tobf16_kernel<<<SS * KK * DD / 4 / 256, 256>>>(cb, cbb, SS * KK * DD / 4);
  // 4. fused cross + filter + exact argmin
  cross_argmin_kernel<<<dim3(BB / 128, SS), 256, FSM_TOT>>>(
      zb, cbb, z, cb, zsq, esq, codes, flags);
  fallback_kernel<<<BB * SS, 256>>>(z, cb, zsq, esq, codes, flags);
  // 5. gather + counts
  gather_kernel<<<BB * SD / 4 / 256, 256>>>(cb, codes, quant);
  zero_kernel<<<SS * KK / 256, 256>>>(counts, SS * KK);
  count_kernel<<<BB * SS / 256, 256>>>(codes, counts);
  // 6. decoder (scaled fp16x3 tensor cores)
  split_kernel<<<IND * SD / 4 / 256, 256>>>(dec_w, dwh, dwl, 32.f,
                                            IND * SD / 4);
  split_kernel<<<BB * SD / 4 / 256, 256>>>(quant, qh, ql, 8192.f,
                                           BB * SD / 4);
  gemm3h<<<dim3(IND / 128, BB / 128), 256>>>(qh, ql, dwh, dwl, dec_b, reconDst,
                                             1.f / (8192.f * 32.f),
                                             BB, IND, SD);
  // 7. tuple tail
  if (out_size >= offC)
    copy4_kernel<<<BB * SD / 4 / 256, 256>>>(out + offQ, quant, BB * SD / 4);
  if (out_size >= offP)
    codesf_kernel<<<BB * SS / 256, 256>>>(out + offC, codes, BB * SS);
  if (out_size >= offP + 1)
    perp_kernel<<<1, 256>>>(counts, out + offP);
}